// round 12
// baseline (speedup 1.0000x reference)
#include <cuda_runtime.h>
#include <cuda_fp16.h>
#include <math.h>

// b=8, c=192, h=w=128, heads=8, ch=24, hw=16384, 3c=576
#define HW 16384
#define C3 576
#define CC 192
#define NB 8
#define KSPL 4    // qk K-split blocks per (b,h)

// Scratch (allocation-free rule: __device__ globals)
__device__ __half   g_qkv_pre[75497472];   // [8,576,16384] fp16
__device__ __half   g_qkv_post[75497472];  // [8,576,16384] fp16
__device__ unsigned g_wh[576 * 96];        // packed w_qkv
__device__ unsigned g_W2h[8 * 192 * 96];   // packed folded proj*attn
__device__ float    g_sumsq[8 * 384];
__device__ float    g_Spart[64 * KSPL * 576];

// ---------------------------------------------------------------------------
__device__ __forceinline__ unsigned pkh(float x, float y) {
    __half2 p = __floats2half2_rn(x, y);
    return *(unsigned*)&p;
}
__device__ __forceinline__ void mma_f16(float* c, const unsigned* a,
                                        unsigned b0, unsigned b1) {
    asm("mma.sync.aligned.m16n8k16.row.col.f32.f16.f16.f32 "
        "{%0,%1,%2,%3}, {%4,%5,%6,%7}, {%8,%9}, {%0,%1,%2,%3};"
        : "+f"(c[0]), "+f"(c[1]), "+f"(c[2]), "+f"(c[3])
        : "r"(a[0]), "r"(a[1]), "r"(a[2]), "r"(a[3]), "r"(b0), "r"(b1));
}

// ---------------------------------------------------------------------------
// w_qkv fp32 [576][192] -> packed u32 [576][96]
__global__ void presplit_w(const float* __restrict__ w, unsigned* __restrict__ wh)
{
    int i = blockIdx.x * 256 + threadIdx.x;
    if (i >= 576 * 96) return;
    int o = i / 96, j = i % 96;
    float2 v = *(const float2*)&w[o * CC + 2 * j];
    wh[i] = pkh(v.x, v.y);
}

// ---------------------------------------------------------------------------
// B-resident fp16 tensor-core GEMM. K fixed = 192. (proven R10, unchanged)
#define BST 136   // Bs row stride (u32)
#define AST 100   // As row stride (u32)
#define ABUF (64 * AST)
__global__ __launch_bounds__(256)
void gemm_nres(const unsigned* __restrict__ Apk, long aBS,
               const void* __restrict__ Bv, long bBS,
               void* __restrict__ Ov, long oBS,
               int M, int N, int BMODE, int HALF_OUT)
{
    extern __shared__ unsigned sh[];
    unsigned* Bs = sh;                 // [96][BST]
    unsigned* As = sh + 96 * BST;      // 2 x [64][AST]

    const int b = blockIdx.y;
    const int n0 = blockIdx.x * 128;
    const unsigned* Ab = Apk + aBS * b;
    const int t = threadIdx.x;
    const int wid = t >> 5, lane = t & 31;
    const int g = lane >> 2, tig = lane & 3;
    const int warp_m = wid >> 2, warp_n = wid & 3;

    if (BMODE == 2) {
        const float* Bf = (const float*)Bv + bBS * b;
#pragma unroll
        for (int j = 0; j < 12; j++) {
            int gi = j * 256 + t;
            int pr = gi >> 5;
            int nc = (gi & 31) * 4;
            const float* base = Bf + (long)(2 * pr) * N + n0 + nc;
            float4 u = *(const float4*)base;
            float4 v = *(const float4*)(base + N);
            *(uint4*)&Bs[pr * BST + nc] =
                make_uint4(pkh(u.x, v.x), pkh(u.y, v.y), pkh(u.z, v.z), pkh(u.w, v.w));
        }
    } else {
        const __half* Bh = (const __half*)Bv + bBS * b;
#pragma unroll
        for (int j = 0; j < 12; j++) {
            int gi = j * 256 + t;
            int pr = gi >> 5;
            int nc = (gi & 31) * 4;
            const __half* base = Bh + (long)(2 * pr) * N + n0 + nc;
            uint2 a = *(const uint2*)base;
            uint2 bb = *(const uint2*)(base + N);
            *(uint4*)&Bs[pr * BST + nc] =
                make_uint4(__byte_perm(a.x, bb.x, 0x5410), __byte_perm(a.x, bb.x, 0x7632),
                           __byte_perm(a.y, bb.y, 0x5410), __byte_perm(a.y, bb.y, 0x7632));
        }
    }
#pragma unroll
    for (int j = 0; j < 6; j++) {
        int gi = j * 256 + t;
        int row = gi / 24;
        int kq = (gi % 24) * 4;
        uint4 v = *(const uint4*)&Ab[(long)row * 96 + kq];
        *(uint4*)&As[row * AST + kq] = v;
    }
    __syncthreads();

    const int mtiles = M / 64;
    int buf = 0;
    for (int mt = 0; mt < mtiles; mt++) {
        const int m0 = mt * 64;
        const bool hasNext = (mt + 1 < mtiles);
        uint4 pf[6];
        if (hasNext) {
#pragma unroll
            for (int j = 0; j < 6; j++) {
                int gi = j * 256 + t;
                int row = gi / 24;
                int kq = (gi % 24) * 4;
                pf[j] = *(const uint4*)&Ab[(long)(m0 + 64 + row) * 96 + kq];
            }
        }

        float c[2][4][4];
#pragma unroll
        for (int i = 0; i < 2; i++)
#pragma unroll
            for (int j = 0; j < 4; j++)
#pragma unroll
                for (int q = 0; q < 4; q++) c[i][j][q] = 0.f;

        const unsigned* Ax = As + buf * ABUF;
#pragma unroll
        for (int kp0 = 0; kp0 < 96; kp0 += 8) {
            unsigned a[2][4];
#pragma unroll
            for (int m2 = 0; m2 < 2; m2++) {
                int rb = warp_m * 32 + m2 * 16;
                a[m2][0] = Ax[(rb + g) * AST + kp0 + tig];
                a[m2][1] = Ax[(rb + g + 8) * AST + kp0 + tig];
                a[m2][2] = Ax[(rb + g) * AST + kp0 + tig + 4];
                a[m2][3] = Ax[(rb + g + 8) * AST + kp0 + tig + 4];
            }
#pragma unroll
            for (int nt = 0; nt < 4; nt++) {
                int gc = warp_n * 32 + nt * 8 + g;
                unsigned b0 = Bs[(kp0 + tig) * BST + gc];
                unsigned b1 = Bs[(kp0 + tig + 4) * BST + gc];
#pragma unroll
                for (int m2 = 0; m2 < 2; m2++)
                    mma_f16(c[m2][nt], a[m2], b0, b1);
            }
        }

        if (hasNext) {
#pragma unroll
            for (int j = 0; j < 6; j++) {
                int gi = j * 256 + t;
                int row = gi / 24;
                int kq = (gi % 24) * 4;
                *(uint4*)&As[(buf ^ 1) * ABUF + row * AST + kq] = pf[j];
            }
        }

#pragma unroll
        for (int m2 = 0; m2 < 2; m2++) {
            int row = m0 + warp_m * 32 + m2 * 16 + g;
#pragma unroll
            for (int nt = 0; nt < 4; nt++) {
                int col = n0 + warp_n * 32 + nt * 8 + 2 * tig;
                if (HALF_OUT) {
                    __half* Oh = (__half*)Ov + oBS * b;
                    *(unsigned*)&Oh[(long)row * N + col] =
                        pkh(c[m2][nt][0], c[m2][nt][1]);
                    *(unsigned*)&Oh[(long)(row + 8) * N + col] =
                        pkh(c[m2][nt][2], c[m2][nt][3]);
                } else {
                    float* Of = (float*)Ov + oBS * b;
                    *(float2*)&Of[(long)row * N + col] =
                        make_float2(c[m2][nt][0], c[m2][nt][1]);
                    *(float2*)&Of[(long)(row + 8) * N + col] =
                        make_float2(c[m2][nt][2], c[m2][nt][3]);
                }
            }
        }
        __syncthreads();
        buf ^= 1;
    }
}

// ---------------------------------------------------------------------------
// Depthwise 3x3 conv (dilation 2, pad 2): one block per (ch, b) plane.
// PROVEN R10 version (half2 smem, scalar fp32 taps, 32KB static smem).
__global__ __launch_bounds__(256)
void dwconv_plane(const __half* __restrict__ in,
                  const float* __restrict__ wdw,
                  __half* __restrict__ out,
                  float* __restrict__ sumsq)
{
    __shared__ __half sp[16384];
    __shared__ float wred[8];
    const int ch = blockIdx.x;
    const int b  = blockIdx.y;
    const int t  = threadIdx.x;
    const __half* ip = in + ((long)b * C3 + ch) * HW;

#pragma unroll
    for (int i = 0; i < 8; i++) {
        int off = (i * 256 + t) * 8;
        *(uint4*)&sp[off] = *(const uint4*)&ip[off];
    }
    float w[9];
#pragma unroll
    for (int i = 0; i < 9; i++) w[i] = __ldg(&wdw[ch * 9 + i]);
    __syncthreads();

    const __half2* sp2 = (const __half2*)sp;
    unsigned* op = (unsigned*)(out + ((long)b * C3 + ch) * HW);
    float ss = 0.f;

#pragma unroll 4
    for (int i = 0; i < 32; i++) {
        int p = i * 512 + t * 2;
        int y = p >> 7, x = p & 127;
        float a0 = 0.f, a1 = 0.f;
#pragma unroll
        for (int r = 0; r < 3; r++) {
            int yy = y + 2 * (r - 1);
            if (yy < 0 || yy >= 128) continue;
            int ro = yy * 64;
            float2 p0 = (x >= 2)
                ? __half22float2(sp2[ro + ((x - 2) >> 1)]) : make_float2(0.f, 0.f);
            float2 p1 = __half22float2(sp2[ro + (x >> 1)]);
            float2 p2 = (x <= 124)
                ? __half22float2(sp2[ro + ((x + 2) >> 1)]) : make_float2(0.f, 0.f);
            float w0 = w[r * 3 + 0], w1 = w[r * 3 + 1], w2 = w[r * 3 + 2];
            a0 += w0 * p0.x + w1 * p1.x + w2 * p2.x;
            a1 += w0 * p0.y + w1 * p1.y + w2 * p2.y;
        }
        op[p >> 1] = pkh(a0, a1);
        ss += a0 * a0 + a1 * a1;
    }

    if (ch < 384) {
#pragma unroll
        for (int off = 16; off; off >>= 1)
            ss += __shfl_down_sync(0xffffffffu, ss, off);
        if ((t & 31) == 0) wred[t >> 5] = ss;
        __syncthreads();
        if (t == 0) {
            float s = 0.f;
#pragma unroll
            for (int i = 0; i < 8; i++) s += wred[i];
            sumsq[b * 384 + ch] = s;
        }
    }
}

// ---------------------------------------------------------------------------
// Tensor-core qk: S = q.k^T (24x24 per (b,h)), KSPL-way K split.
// Both q and k staged by DIRECT uint4 copy ([channel][spatial] rows, u32 =
// spatial fp16 pair). Fragment scheme identical to proven gemm_nres
// (stride 132 == 4 mod 32: conflict-free). M padded to 32, pad rows zeroed.
// 8 warps split the 256-col stage; deterministic 8-slab tree reduction.
#define QAST 132
__global__ __launch_bounds__(256)
void qk_mma(const __half* __restrict__ qkv, float* __restrict__ Spart)
{
    __shared__ unsigned Aq[32 * QAST];   // q rows 0..23 + zero pad 24..31
    __shared__ unsigned Bk[24 * QAST];   // k rows
    __shared__ float Sred[8][576];

    const int split = blockIdx.x;        // 0..KSPL-1
    const int bh    = blockIdx.y;        // 0..63
    const int b = bh >> 3, h = bh & 7;
    const __half* qp = qkv + ((long)b * C3 + h * 24) * HW;
    const __half* kp = qkv + ((long)b * C3 + 192 + h * 24) * HW;
    const int t = threadIdx.x;
    const int wid = t >> 5, lane = t & 31;
    const int g = lane >> 2, tig = lane & 3;

    // zero the pad rows (written once; staging only touches rows 0..23)
    for (int i = t; i < 8 * QAST; i += 256) Aq[24 * QAST + i] = 0;

    float c[2][3][4];
#pragma unroll
    for (int i = 0; i < 2; i++)
#pragma unroll
        for (int j = 0; j < 3; j++)
#pragma unroll
            for (int q = 0; q < 4; q++) c[i][j][q] = 0.f;

    int n0 = split * (HW / KSPL);
    const int stages = (HW / KSPL) / 256;
    for (int st = 0; st < stages; st++, n0 += 256) {
        __syncthreads();  // pad-zero visible / prior-stage reads done
        // stage q,k: 1536 uint4 tasks (q: 0..767, k: 768..1535), direct copy
#pragma unroll
        for (int j = 0; j < 6; j++) {
            int gi = j * 256 + t;
            int isk = gi >= 768;
            int li = isk ? gi - 768 : gi;
            int r = li >> 5, c4 = li & 31;
            const __half* src = (isk ? kp : qp) + (long)r * HW + n0 + c4 * 8;
            uint4 v = *(const uint4*)src;
            unsigned* dst = (isk ? Bk : Aq) + r * QAST + c4 * 4;
            *(uint4*)dst = v;
        }
        __syncthreads();

        // warp wid covers k-pairs [s2*64 + wid*8, +8) : 2 steps of k=16
#pragma unroll
        for (int s2 = 0; s2 < 2; s2++) {
            int kp0 = s2 * 64 + wid * 8;
            unsigned a[2][4];
#pragma unroll
            for (int m2 = 0; m2 < 2; m2++) {
                int rb = m2 * 16;
                a[m2][0] = Aq[(rb + g) * QAST + kp0 + tig];
                a[m2][1] = Aq[(rb + g + 8) * QAST + kp0 + tig];
                a[m2][2] = Aq[(rb + g) * QAST + kp0 + tig + 4];
                a[m2][3] = Aq[(rb + g + 8) * QAST + kp0 + tig + 4];
            }
#pragma unroll
            for (int nt = 0; nt < 3; nt++) {
                int gc = nt * 8 + g;
                unsigned b0 = Bk[gc * QAST + kp0 + tig];
                unsigned b1 = Bk[gc * QAST + kp0 + tig + 4];
#pragma unroll
                for (int m2 = 0; m2 < 2; m2++)
                    mma_f16(c[m2][nt], a[m2], b0, b1);
            }
        }
    }

    // per-warp partials -> slabs (rows >= 24 discarded)
#pragma unroll
    for (int m2 = 0; m2 < 2; m2++)
#pragma unroll
        for (int hf = 0; hf < 2; hf++) {
            int row = m2 * 16 + hf * 8 + g;
            if (row < 24) {
#pragma unroll
                for (int nt = 0; nt < 3; nt++) {
                    int col = nt * 8 + 2 * tig;
                    *(float2*)&Sred[wid][row * 24 + col] =
                        make_float2(c[m2][nt][hf * 2], c[m2][nt][hf * 2 + 1]);
                }
            }
        }
    __syncthreads();

    float* sp = Spart + ((long)bh * KSPL + split) * 576;
    for (int i = t; i < 576; i += 256) {
        float s01 = Sred[0][i] + Sred[1][i];
        float s23 = Sred[2][i] + Sred[3][i];
        float s45 = Sred[4][i] + Sred[5][i];
        float s67 = Sred[6][i] + Sred[7][i];
        sp[i] = (s01 + s23) + (s45 + s67);
    }
}

// ---------------------------------------------------------------------------
// Per (b,head): reduce split-K, normalize, softmax, fold w_proj -> fp16 W2.
__global__ void softmax_fold_kernel(const float* __restrict__ Spart,
                                    const float* __restrict__ sumsq,
                                    const float* __restrict__ temp,
                                    const float* __restrict__ wproj,
                                    unsigned* __restrict__ W2h)
{
    const int bh = blockIdx.x;          // 0..63
    const int b = bh >> 3, h = bh & 7;
    const int t = threadIdx.x;          // 256
    __shared__ float A[576];
    __shared__ float nq[24], nk[24];
    if (t < 24)
        nq[t] = sqrtf(sumsq[b * 384 + h * 24 + t]) + 1e-6f;
    else if (t < 48)
        nk[t - 24] = sqrtf(sumsq[b * 384 + 192 + h * 24 + (t - 24)]) + 1e-6f;
    __syncthreads();
    const float tmp = temp[h];
    for (int r = t; r < 576; r += 256) {
        int cidx = r / 24, d = r % 24;
        float s = 0.f;
#pragma unroll
        for (int ck = 0; ck < KSPL; ck++)
            s += Spart[((long)bh * KSPL + ck) * 576 + r];
        A[r] = s / (nq[cidx] * nk[d]) * tmp;
    }
    __syncthreads();
    if (t < 24) {
        float* row = &A[t * 24];
        float m = row[0];
        for (int d = 1; d < 24; d++) m = fmaxf(m, row[d]);
        float s = 0.f;
        for (int d = 0; d < 24; d++) { float e = expf(row[d] - m); row[d] = e; s += e; }
        float inv = 1.f / s;
        for (int d = 0; d < 24; d++) row[d] *= inv;
    }
    __syncthreads();
    for (int idx = t; idx < 192 * 12; idx += 256) {
        int o = idx / 12, jj = idx % 12;
        int d0 = 2 * jj;
        float s0 = 0.f, s1 = 0.f;
#pragma unroll
        for (int cidx = 0; cidx < 24; cidx++) {
            float wv = wproj[o * CC + h * 24 + cidx];
            s0 += wv * A[cidx * 24 + d0];
            s1 += wv * A[cidx * 24 + d0 + 1];
        }
        W2h[((long)b * CC + o) * 96 + h * 12 + jj] = pkh(s0, s1);
    }
}

// ---------------------------------------------------------------------------
extern "C" void kernel_launch(void* const* d_in, const int* in_sizes, int n_in,
                              void* d_out, int out_size)
{
    const float* x      = (const float*)d_in[0];
    const float* w_qkv  = (const float*)d_in[1];
    const float* w_dw   = (const float*)d_in[2];
    const float* w_proj = (const float*)d_in[3];
    const float* temp   = (const float*)d_in[4];
    float* out = (float*)d_out;

    __half *qkv_pre, *qkv_post;
    unsigned *wh, *W2h;
    float *sumsq, *Spart;
    cudaGetSymbolAddress((void**)&qkv_pre,  g_qkv_pre);
    cudaGetSymbolAddress((void**)&qkv_post, g_qkv_post);
    cudaGetSymbolAddress((void**)&wh,       g_wh);
    cudaGetSymbolAddress((void**)&W2h,      g_W2h);
    cudaGetSymbolAddress((void**)&sumsq,    g_sumsq);
    cudaGetSymbolAddress((void**)&Spart,    g_Spart);

    const int SMEM = (96 * BST + 2 * 64 * AST) * 4;  // 103424 B
    cudaFuncSetAttribute(gemm_nres,
                         cudaFuncAttributeMaxDynamicSharedMemorySize, SMEM);

    presplit_w<<<(576 * 96 + 255) / 256, 256>>>(w_qkv, wh);

    // K1: qkv = w_qkv @ x  -> fp16 (B resident, double-buffered A)
    gemm_nres<<<dim3(HW / 128, NB), 256, SMEM>>>(
        wh, 0L, x, (long)CC * HW, qkv_pre, (long)C3 * HW, C3, HW, 2, 1);

    // K2: depthwise conv (proven R10) + block-reduced sumsq
    dwconv_plane<<<dim3(C3, NB), 256>>>(qkv_pre, w_dw, qkv_post, sumsq);

    // K3: tensor-core q.k^T (gemm-pattern fragments, no-transpose staging)
    qk_mma<<<dim3(KSPL, 64), 256>>>(qkv_post, Spart);

    // K4: per-(b,h) normalize + softmax + fold -> packed fp16 W2
    softmax_fold_kernel<<<64, 256>>>(Spart, sumsq, temp, w_proj, W2h);

    // K5: out = W2 @ v  (B = v resident fp16), fp32 out
    gemm_nres<<<dim3(HW / 128, NB), 256, SMEM>>>(
        W2h, (long)CC * 96, qkv_post + 384L * HW, (long)C3 * HW,
        out, (long)CC * HW, CC, HW, 1, 0);
}

// round 14
// speedup vs baseline: 1.4958x; 1.4958x over previous
#include <cuda_runtime.h>
#include <cuda_fp16.h>
#include <math.h>

// b=8, c=192, h=w=128, heads=8, ch=24, hw=16384, 3c=576
#define HW 16384
#define C3 576
#define CC 192
#define NB 8
#define KSPL 8    // qk K-split blocks per (b,h)

// Scratch (allocation-free rule: __device__ globals)
__device__ __half   g_qkv_pre[75497472];   // [8,576,16384] fp16
__device__ __half   g_qkv_post[75497472];  // [8,576,16384] fp16
__device__ unsigned g_wh[576 * 96];        // packed w_qkv
__device__ unsigned g_W2h[8 * 192 * 96];   // packed folded proj*attn
__device__ float    g_sumsq[8 * 384];
__device__ float    g_Spart[64 * KSPL * 576];

// ---------------------------------------------------------------------------
__device__ __forceinline__ unsigned pkh(float x, float y) {
    __half2 p = __floats2half2_rn(x, y);
    return *(unsigned*)&p;
}
__device__ __forceinline__ void mma_f16(float* c, const unsigned* a,
                                        unsigned b0, unsigned b1) {
    asm("mma.sync.aligned.m16n8k16.row.col.f32.f16.f16.f32 "
        "{%0,%1,%2,%3}, {%4,%5,%6,%7}, {%8,%9}, {%0,%1,%2,%3};"
        : "+f"(c[0]), "+f"(c[1]), "+f"(c[2]), "+f"(c[3])
        : "r"(a[0]), "r"(a[1]), "r"(a[2]), "r"(a[3]), "r"(b0), "r"(b1));
}

// ---------------------------------------------------------------------------
// w_qkv fp32 [576][192] -> packed u32 [576][96]
__global__ void presplit_w(const float* __restrict__ w, unsigned* __restrict__ wh)
{
    int i = blockIdx.x * 256 + threadIdx.x;
    if (i >= 576 * 96) return;
    int o = i / 96, j = i % 96;
    float2 v = *(const float2*)&w[o * CC + 2 * j];
    wh[i] = pkh(v.x, v.y);
}

// ---------------------------------------------------------------------------
// B-resident fp16 tensor-core GEMM. K fixed = 192. (proven R10, unchanged)
#define BST 136   // Bs row stride (u32)
#define AST 100   // As row stride (u32)
#define ABUF (64 * AST)
__global__ __launch_bounds__(256)
void gemm_nres(const unsigned* __restrict__ Apk, long aBS,
               const void* __restrict__ Bv, long bBS,
               void* __restrict__ Ov, long oBS,
               int M, int N, int BMODE, int HALF_OUT)
{
    extern __shared__ unsigned sh[];
    unsigned* Bs = sh;                 // [96][BST]
    unsigned* As = sh + 96 * BST;      // 2 x [64][AST]

    const int b = blockIdx.y;
    const int n0 = blockIdx.x * 128;
    const unsigned* Ab = Apk + aBS * b;
    const int t = threadIdx.x;
    const int wid = t >> 5, lane = t & 31;
    const int g = lane >> 2, tig = lane & 3;
    const int warp_m = wid >> 2, warp_n = wid & 3;

    if (BMODE == 2) {
        const float* Bf = (const float*)Bv + bBS * b;
#pragma unroll
        for (int j = 0; j < 12; j++) {
            int gi = j * 256 + t;
            int pr = gi >> 5;
            int nc = (gi & 31) * 4;
            const float* base = Bf + (long)(2 * pr) * N + n0 + nc;
            float4 u = *(const float4*)base;
            float4 v = *(const float4*)(base + N);
            *(uint4*)&Bs[pr * BST + nc] =
                make_uint4(pkh(u.x, v.x), pkh(u.y, v.y), pkh(u.z, v.z), pkh(u.w, v.w));
        }
    } else {
        const __half* Bh = (const __half*)Bv + bBS * b;
#pragma unroll
        for (int j = 0; j < 12; j++) {
            int gi = j * 256 + t;
            int pr = gi >> 5;
            int nc = (gi & 31) * 4;
            const __half* base = Bh + (long)(2 * pr) * N + n0 + nc;
            uint2 a = *(const uint2*)base;
            uint2 bb = *(const uint2*)(base + N);
            *(uint4*)&Bs[pr * BST + nc] =
                make_uint4(__byte_perm(a.x, bb.x, 0x5410), __byte_perm(a.x, bb.x, 0x7632),
                           __byte_perm(a.y, bb.y, 0x5410), __byte_perm(a.y, bb.y, 0x7632));
        }
    }
#pragma unroll
    for (int j = 0; j < 6; j++) {
        int gi = j * 256 + t;
        int row = gi / 24;
        int kq = (gi % 24) * 4;
        uint4 v = *(const uint4*)&Ab[(long)row * 96 + kq];
        *(uint4*)&As[row * AST + kq] = v;
    }
    __syncthreads();

    const int mtiles = M / 64;
    int buf = 0;
    for (int mt = 0; mt < mtiles; mt++) {
        const int m0 = mt * 64;
        const bool hasNext = (mt + 1 < mtiles);
        uint4 pf[6];
        if (hasNext) {
#pragma unroll
            for (int j = 0; j < 6; j++) {
                int gi = j * 256 + t;
                int row = gi / 24;
                int kq = (gi % 24) * 4;
                pf[j] = *(const uint4*)&Ab[(long)(m0 + 64 + row) * 96 + kq];
            }
        }

        float c[2][4][4];
#pragma unroll
        for (int i = 0; i < 2; i++)
#pragma unroll
            for (int j = 0; j < 4; j++)
#pragma unroll
                for (int q = 0; q < 4; q++) c[i][j][q] = 0.f;

        const unsigned* Ax = As + buf * ABUF;
#pragma unroll
        for (int kp0 = 0; kp0 < 96; kp0 += 8) {
            unsigned a[2][4];
#pragma unroll
            for (int m2 = 0; m2 < 2; m2++) {
                int rb = warp_m * 32 + m2 * 16;
                a[m2][0] = Ax[(rb + g) * AST + kp0 + tig];
                a[m2][1] = Ax[(rb + g + 8) * AST + kp0 + tig];
                a[m2][2] = Ax[(rb + g) * AST + kp0 + tig + 4];
                a[m2][3] = Ax[(rb + g + 8) * AST + kp0 + tig + 4];
            }
#pragma unroll
            for (int nt = 0; nt < 4; nt++) {
                int gc = warp_n * 32 + nt * 8 + g;
                unsigned b0 = Bs[(kp0 + tig) * BST + gc];
                unsigned b1 = Bs[(kp0 + tig + 4) * BST + gc];
#pragma unroll
                for (int m2 = 0; m2 < 2; m2++)
                    mma_f16(c[m2][nt], a[m2], b0, b1);
            }
        }

        if (hasNext) {
#pragma unroll
            for (int j = 0; j < 6; j++) {
                int gi = j * 256 + t;
                int row = gi / 24;
                int kq = (gi % 24) * 4;
                *(uint4*)&As[(buf ^ 1) * ABUF + row * AST + kq] = pf[j];
            }
        }

#pragma unroll
        for (int m2 = 0; m2 < 2; m2++) {
            int row = m0 + warp_m * 32 + m2 * 16 + g;
#pragma unroll
            for (int nt = 0; nt < 4; nt++) {
                int col = n0 + warp_n * 32 + nt * 8 + 2 * tig;
                if (HALF_OUT) {
                    __half* Oh = (__half*)Ov + oBS * b;
                    *(unsigned*)&Oh[(long)row * N + col] =
                        pkh(c[m2][nt][0], c[m2][nt][1]);
                    *(unsigned*)&Oh[(long)(row + 8) * N + col] =
                        pkh(c[m2][nt][2], c[m2][nt][3]);
                } else {
                    float* Of = (float*)Ov + oBS * b;
                    *(float2*)&Of[(long)row * N + col] =
                        make_float2(c[m2][nt][0], c[m2][nt][1]);
                    *(float2*)&Of[(long)(row + 8) * N + col] =
                        make_float2(c[m2][nt][2], c[m2][nt][3]);
                }
            }
        }
        __syncthreads();
        buf ^= 1;
    }
}

// ---------------------------------------------------------------------------
// Depthwise 3x3 conv (dilation 2, pad 2): one block per (ch, b) plane.
// PROVEN R10 version (half2 smem, scalar fp32 taps, 32KB static smem).
__global__ __launch_bounds__(256)
void dwconv_plane(const __half* __restrict__ in,
                  const float* __restrict__ wdw,
                  __half* __restrict__ out,
                  float* __restrict__ sumsq)
{
    __shared__ __half sp[16384];
    __shared__ float wred[8];
    const int ch = blockIdx.x;
    const int b  = blockIdx.y;
    const int t  = threadIdx.x;
    const __half* ip = in + ((long)b * C3 + ch) * HW;

#pragma unroll
    for (int i = 0; i < 8; i++) {
        int off = (i * 256 + t) * 8;
        *(uint4*)&sp[off] = *(const uint4*)&ip[off];
    }
    float w[9];
#pragma unroll
    for (int i = 0; i < 9; i++) w[i] = __ldg(&wdw[ch * 9 + i]);
    __syncthreads();

    const __half2* sp2 = (const __half2*)sp;
    unsigned* op = (unsigned*)(out + ((long)b * C3 + ch) * HW);
    float ss = 0.f;

#pragma unroll 4
    for (int i = 0; i < 32; i++) {
        int p = i * 512 + t * 2;
        int y = p >> 7, x = p & 127;
        float a0 = 0.f, a1 = 0.f;
#pragma unroll
        for (int r = 0; r < 3; r++) {
            int yy = y + 2 * (r - 1);
            if (yy < 0 || yy >= 128) continue;
            int ro = yy * 64;
            float2 p0 = (x >= 2)
                ? __half22float2(sp2[ro + ((x - 2) >> 1)]) : make_float2(0.f, 0.f);
            float2 p1 = __half22float2(sp2[ro + (x >> 1)]);
            float2 p2 = (x <= 124)
                ? __half22float2(sp2[ro + ((x + 2) >> 1)]) : make_float2(0.f, 0.f);
            float w0 = w[r * 3 + 0], w1 = w[r * 3 + 1], w2 = w[r * 3 + 2];
            a0 += w0 * p0.x + w1 * p1.x + w2 * p2.x;
            a1 += w0 * p0.y + w1 * p1.y + w2 * p2.y;
        }
        op[p >> 1] = pkh(a0, a1);
        ss += a0 * a0 + a1 * a1;
    }

    if (ch < 384) {
#pragma unroll
        for (int off = 16; off; off >>= 1)
            ss += __shfl_down_sync(0xffffffffu, ss, off);
        if ((t & 31) == 0) wred[t >> 5] = ss;
        __syncthreads();
        if (t == 0) {
            float s = 0.f;
#pragma unroll
            for (int i = 0; i < 8; i++) s += wred[i];
            sumsq[b * 384 + ch] = s;
        }
    }
}

// ---------------------------------------------------------------------------
// Tensor-core qk: S = q.k^T (24x24 per (b,h)), KSPL-way K split. (R12 proven)
#define QAST 132
__global__ __launch_bounds__(256)
void qk_mma(const __half* __restrict__ qkv, float* __restrict__ Spart)
{
    __shared__ unsigned Aq[32 * QAST];   // q rows 0..23 + zero pad 24..31
    __shared__ unsigned Bk[24 * QAST];   // k rows
    __shared__ float Sred[8][576];

    const int split = blockIdx.x;        // 0..KSPL-1
    const int bh    = blockIdx.y;        // 0..63
    const int b = bh >> 3, h = bh & 7;
    const __half* qp = qkv + ((long)b * C3 + h * 24) * HW;
    const __half* kp = qkv + ((long)b * C3 + 192 + h * 24) * HW;
    const int t = threadIdx.x;
    const int wid = t >> 5, lane = t & 31;
    const int g = lane >> 2, tig = lane & 3;

    for (int i = t; i < 8 * QAST; i += 256) Aq[24 * QAST + i] = 0;

    float c[2][3][4];
#pragma unroll
    for (int i = 0; i < 2; i++)
#pragma unroll
        for (int j = 0; j < 3; j++)
#pragma unroll
            for (int q = 0; q < 4; q++) c[i][j][q] = 0.f;

    int n0 = split * (HW / KSPL);
    const int stages = (HW / KSPL) / 256;
    for (int st = 0; st < stages; st++, n0 += 256) {
        __syncthreads();
#pragma unroll
        for (int j = 0; j < 6; j++) {
            int gi = j * 256 + t;
            int isk = gi >= 768;
            int li = isk ? gi - 768 : gi;
            int r = li >> 5, c4 = li & 31;
            const __half* src = (isk ? kp : qp) + (long)r * HW + n0 + c4 * 8;
            uint4 v = *(const uint4*)src;
            unsigned* dst = (isk ? Bk : Aq) + r * QAST + c4 * 4;
            *(uint4*)dst = v;
        }
        __syncthreads();

#pragma unroll
        for (int s2 = 0; s2 < 2; s2++) {
            int kp0 = s2 * 64 + wid * 8;
            unsigned a[2][4];
#pragma unroll
            for (int m2 = 0; m2 < 2; m2++) {
                int rb = m2 * 16;
                a[m2][0] = Aq[(rb + g) * QAST + kp0 + tig];
                a[m2][1] = Aq[(rb + g + 8) * QAST + kp0 + tig];
                a[m2][2] = Aq[(rb + g) * QAST + kp0 + tig + 4];
                a[m2][3] = Aq[(rb + g + 8) * QAST + kp0 + tig + 4];
            }
#pragma unroll
            for (int nt = 0; nt < 3; nt++) {
                int gc = nt * 8 + g;
                unsigned b0 = Bk[gc * QAST + kp0 + tig];
                unsigned b1 = Bk[gc * QAST + kp0 + tig + 4];
#pragma unroll
                for (int m2 = 0; m2 < 2; m2++)
                    mma_f16(c[m2][nt], a[m2], b0, b1);
            }
        }
    }

#pragma unroll
    for (int m2 = 0; m2 < 2; m2++)
#pragma unroll
        for (int hf = 0; hf < 2; hf++) {
            int row = m2 * 16 + hf * 8 + g;
            if (row < 24) {
#pragma unroll
                for (int nt = 0; nt < 3; nt++) {
                    int col = nt * 8 + 2 * tig;
                    *(float2*)&Sred[wid][row * 24 + col] =
                        make_float2(c[m2][nt][hf * 2], c[m2][nt][hf * 2 + 1]);
                }
            }
        }
    __syncthreads();

    float* sp = Spart + ((long)bh * KSPL + split) * 576;
    for (int i = t; i < 576; i += 256) {
        float s01 = Sred[0][i] + Sred[1][i];
        float s23 = Sred[2][i] + Sred[3][i];
        float s45 = Sred[4][i] + Sred[5][i];
        float s67 = Sred[6][i] + Sred[7][i];
        sp[i] = (s01 + s23) + (s45 + s67);
    }
}

// ---------------------------------------------------------------------------
// Per (b,head): reduce split-K, normalize, softmax, fold w_proj -> fp16 W2.
__global__ void softmax_fold_kernel(const float* __restrict__ Spart,
                                    const float* __restrict__ sumsq,
                                    const float* __restrict__ temp,
                                    const float* __restrict__ wproj,
                                    unsigned* __restrict__ W2h)
{
    const int bh = blockIdx.x;          // 0..63
    const int b = bh >> 3, h = bh & 7;
    const int t = threadIdx.x;          // 256
    __shared__ float A[576];
    __shared__ float nq[24], nk[24];
    if (t < 24)
        nq[t] = sqrtf(sumsq[b * 384 + h * 24 + t]) + 1e-6f;
    else if (t < 48)
        nk[t - 24] = sqrtf(sumsq[b * 384 + 192 + h * 24 + (t - 24)]) + 1e-6f;
    __syncthreads();
    const float tmp = temp[h];
    for (int r = t; r < 576; r += 256) {
        int cidx = r / 24, d = r % 24;
        float s = 0.f;
#pragma unroll
        for (int ck = 0; ck < KSPL; ck++)
            s += Spart[((long)bh * KSPL + ck) * 576 + r];
        A[r] = s / (nq[cidx] * nk[d]) * tmp;
    }
    __syncthreads();
    if (t < 24) {
        float* row = &A[t * 24];
        float m = row[0];
        for (int d = 1; d < 24; d++) m = fmaxf(m, row[d]);
        float s = 0.f;
        for (int d = 0; d < 24; d++) { float e = expf(row[d] - m); row[d] = e; s += e; }
        float inv = 1.f / s;
        for (int d = 0; d < 24; d++) row[d] *= inv;
    }
    __syncthreads();
    for (int idx = t; idx < 192 * 12; idx += 256) {
        int o = idx / 12, jj = idx % 12;
        int d0 = 2 * jj;
        float s0 = 0.f, s1 = 0.f;
#pragma unroll
        for (int cidx = 0; cidx < 24; cidx++) {
            float wv = wproj[o * CC + h * 24 + cidx];
            s0 += wv * A[cidx * 24 + d0];
            s1 += wv * A[cidx * 24 + d0 + 1];
        }
        W2h[((long)b * CC + o) * 96 + h * 12 + jj] = pkh(s0, s1);
    }
}

// ---------------------------------------------------------------------------
extern "C" void kernel_launch(void* const* d_in, const int* in_sizes, int n_in,
                              void* d_out, int out_size)
{
    const float* x      = (const float*)d_in[0];
    const float* w_qkv  = (const float*)d_in[1];
    const float* w_dw   = (const float*)d_in[2];
    const float* w_proj = (const float*)d_in[3];
    const float* temp   = (const float*)d_in[4];
    float* out = (float*)d_out;

    __half *qkv_pre, *qkv_post;
    unsigned *wh, *W2h;
    float *sumsq, *Spart;
    cudaGetSymbolAddress((void**)&qkv_pre,  g_qkv_pre);
    cudaGetSymbolAddress((void**)&qkv_post, g_qkv_post);
    cudaGetSymbolAddress((void**)&wh,       g_wh);
    cudaGetSymbolAddress((void**)&W2h,      g_W2h);
    cudaGetSymbolAddress((void**)&sumsq,    g_sumsq);
    cudaGetSymbolAddress((void**)&Spart,    g_Spart);

    const int SMEM = (96 * BST + 2 * 64 * AST) * 4;  // 103424 B
    cudaFuncSetAttribute(gemm_nres,
                         cudaFuncAttributeMaxDynamicSharedMemorySize, SMEM);

    presplit_w<<<(576 * 96 + 255) / 256, 256>>>(w_qkv, wh);

    // K1: qkv = w_qkv @ x  -> fp16 (B resident, double-buffered A)
    gemm_nres<<<dim3(HW / 128, NB), 256, SMEM>>>(
        wh, 0L, x, (long)CC * HW, qkv_pre, (long)C3 * HW, C3, HW, 2, 1);

    // K2: depthwise conv (proven R10) + block-reduced sumsq
    dwconv_plane<<<dim3(C3, NB), 256>>>(qkv_pre, w_dw, qkv_post, sumsq);

    // K3: tensor-core q.k^T (KSPL=8: 512 blocks, shorter tail)
    qk_mma<<<dim3(KSPL, 64), 256>>>(qkv_post, Spart);

    // K4: per-(b,h) normalize + softmax + fold -> packed fp16 W2
    softmax_fold_kernel<<<64, 256>>>(Spart, sumsq, temp, w_proj, W2h);

    // K5: out = W2 @ v  (B = v resident fp16), fp32 out
    gemm_nres<<<dim3(HW / 128, NB), 256, SMEM>>>(
        W2h, (long)CC * 96, qkv_post + 384L * HW, (long)C3 * HW,
        out, (long)CC * HW, CC, HW, 1, 0);
}

// round 15
// speedup vs baseline: 1.6678x; 1.1150x over previous
#include <cuda_runtime.h>
#include <cuda_fp16.h>
#include <math.h>

// b=8, c=192, h=w=128, heads=8, ch=24, hw=16384, 3c=576
#define HW 16384
#define C3 576
#define CC 192
#define NB 8
#define KSPL 8    // qk K-split blocks per (b,h)

// Scratch (allocation-free rule: __device__ globals)
__device__ __half   g_qkv_pre[75497472];   // [8,576,16384] fp16
__device__ __half   g_qkv_post[75497472];  // [8,576,16384] fp16
__device__ unsigned g_wh[576 * 96];        // packed w_qkv
__device__ unsigned g_W2h[8 * 192 * 96];   // packed folded proj*attn
__device__ float    g_sumsq[8 * 384];
__device__ float    g_Spart[64 * KSPL * 576];

// ---------------------------------------------------------------------------
__device__ __forceinline__ unsigned pkh(float x, float y) {
    __half2 p = __floats2half2_rn(x, y);
    return *(unsigned*)&p;
}
__device__ __forceinline__ void mma_f16(float* c, const unsigned* a,
                                        unsigned b0, unsigned b1) {
    asm("mma.sync.aligned.m16n8k16.row.col.f32.f16.f16.f32 "
        "{%0,%1,%2,%3}, {%4,%5,%6,%7}, {%8,%9}, {%0,%1,%2,%3};"
        : "+f"(c[0]), "+f"(c[1]), "+f"(c[2]), "+f"(c[3])
        : "r"(a[0]), "r"(a[1]), "r"(a[2]), "r"(a[3]), "r"(b0), "r"(b1));
}

// ---------------------------------------------------------------------------
// w_qkv fp32 [576][192] -> packed u32 [576][96]
__global__ void presplit_w(const float* __restrict__ w, unsigned* __restrict__ wh)
{
    int i = blockIdx.x * 256 + threadIdx.x;
    if (i >= 576 * 96) return;
    int o = i / 96, j = i % 96;
    float2 v = *(const float2*)&w[o * CC + 2 * j];
    wh[i] = pkh(v.x, v.y);
}

// ---------------------------------------------------------------------------
// B-resident fp16 tensor-core GEMM. K fixed = 192. (proven R10, unchanged)
#define BST 136   // Bs row stride (u32)
#define AST 100   // As row stride (u32)
#define ABUF (64 * AST)
__global__ __launch_bounds__(256)
void gemm_nres(const unsigned* __restrict__ Apk, long aBS,
               const void* __restrict__ Bv, long bBS,
               void* __restrict__ Ov, long oBS,
               int M, int N, int BMODE, int HALF_OUT)
{
    extern __shared__ unsigned sh[];
    unsigned* Bs = sh;                 // [96][BST]
    unsigned* As = sh + 96 * BST;      // 2 x [64][AST]

    const int b = blockIdx.y;
    const int n0 = blockIdx.x * 128;
    const unsigned* Ab = Apk + aBS * b;
    const int t = threadIdx.x;
    const int wid = t >> 5, lane = t & 31;
    const int g = lane >> 2, tig = lane & 3;
    const int warp_m = wid >> 2, warp_n = wid & 3;

    if (BMODE == 2) {
        const float* Bf = (const float*)Bv + bBS * b;
#pragma unroll
        for (int j = 0; j < 12; j++) {
            int gi = j * 256 + t;
            int pr = gi >> 5;
            int nc = (gi & 31) * 4;
            const float* base = Bf + (long)(2 * pr) * N + n0 + nc;
            float4 u = *(const float4*)base;
            float4 v = *(const float4*)(base + N);
            *(uint4*)&Bs[pr * BST + nc] =
                make_uint4(pkh(u.x, v.x), pkh(u.y, v.y), pkh(u.z, v.z), pkh(u.w, v.w));
        }
    } else {
        const __half* Bh = (const __half*)Bv + bBS * b;
#pragma unroll
        for (int j = 0; j < 12; j++) {
            int gi = j * 256 + t;
            int pr = gi >> 5;
            int nc = (gi & 31) * 4;
            const __half* base = Bh + (long)(2 * pr) * N + n0 + nc;
            uint2 a = *(const uint2*)base;
            uint2 bb = *(const uint2*)(base + N);
            *(uint4*)&Bs[pr * BST + nc] =
                make_uint4(__byte_perm(a.x, bb.x, 0x5410), __byte_perm(a.x, bb.x, 0x7632),
                           __byte_perm(a.y, bb.y, 0x5410), __byte_perm(a.y, bb.y, 0x7632));
        }
    }
#pragma unroll
    for (int j = 0; j < 6; j++) {
        int gi = j * 256 + t;
        int row = gi / 24;
        int kq = (gi % 24) * 4;
        uint4 v = *(const uint4*)&Ab[(long)row * 96 + kq];
        *(uint4*)&As[row * AST + kq] = v;
    }
    __syncthreads();

    const int mtiles = M / 64;
    int buf = 0;
    for (int mt = 0; mt < mtiles; mt++) {
        const int m0 = mt * 64;
        const bool hasNext = (mt + 1 < mtiles);
        uint4 pf[6];
        if (hasNext) {
#pragma unroll
            for (int j = 0; j < 6; j++) {
                int gi = j * 256 + t;
                int row = gi / 24;
                int kq = (gi % 24) * 4;
                pf[j] = *(const uint4*)&Ab[(long)(m0 + 64 + row) * 96 + kq];
            }
        }

        float c[2][4][4];
#pragma unroll
        for (int i = 0; i < 2; i++)
#pragma unroll
            for (int j = 0; j < 4; j++)
#pragma unroll
                for (int q = 0; q < 4; q++) c[i][j][q] = 0.f;

        const unsigned* Ax = As + buf * ABUF;
#pragma unroll
        for (int kp0 = 0; kp0 < 96; kp0 += 8) {
            unsigned a[2][4];
#pragma unroll
            for (int m2 = 0; m2 < 2; m2++) {
                int rb = warp_m * 32 + m2 * 16;
                a[m2][0] = Ax[(rb + g) * AST + kp0 + tig];
                a[m2][1] = Ax[(rb + g + 8) * AST + kp0 + tig];
                a[m2][2] = Ax[(rb + g) * AST + kp0 + tig + 4];
                a[m2][3] = Ax[(rb + g + 8) * AST + kp0 + tig + 4];
            }
#pragma unroll
            for (int nt = 0; nt < 4; nt++) {
                int gc = warp_n * 32 + nt * 8 + g;
                unsigned b0 = Bs[(kp0 + tig) * BST + gc];
                unsigned b1 = Bs[(kp0 + tig + 4) * BST + gc];
#pragma unroll
                for (int m2 = 0; m2 < 2; m2++)
                    mma_f16(c[m2][nt], a[m2], b0, b1);
            }
        }

        if (hasNext) {
#pragma unroll
            for (int j = 0; j < 6; j++) {
                int gi = j * 256 + t;
                int row = gi / 24;
                int kq = (gi % 24) * 4;
                *(uint4*)&As[(buf ^ 1) * ABUF + row * AST + kq] = pf[j];
            }
        }

#pragma unroll
        for (int m2 = 0; m2 < 2; m2++) {
            int row = m0 + warp_m * 32 + m2 * 16 + g;
#pragma unroll
            for (int nt = 0; nt < 4; nt++) {
                int col = n0 + warp_n * 32 + nt * 8 + 2 * tig;
                if (HALF_OUT) {
                    __half* Oh = (__half*)Ov + oBS * b;
                    *(unsigned*)&Oh[(long)row * N + col] =
                        pkh(c[m2][nt][0], c[m2][nt][1]);
                    *(unsigned*)&Oh[(long)(row + 8) * N + col] =
                        pkh(c[m2][nt][2], c[m2][nt][3]);
                } else {
                    float* Of = (float*)Ov + oBS * b;
                    *(float2*)&Of[(long)row * N + col] =
                        make_float2(c[m2][nt][0], c[m2][nt][1]);
                    *(float2*)&Of[(long)(row + 8) * N + col] =
                        make_float2(c[m2][nt][2], c[m2][nt][3]);
                }
            }
        }
        __syncthreads();
        buf ^= 1;
    }
}

// ---------------------------------------------------------------------------
// Depthwise 3x3 conv (dilation 2, pad 2): one block per (ch, b) plane.
// Column-strip iteration with rolling row registers: each staged half2 is
// loaded+converted ONCE (vs 3x). Per-output FMA order unchanged (top/mid/bot,
// identical operand order; OOB rows contribute exact zeros) => bit-identical.
__device__ __forceinline__ void dw_load_row(const __half2* sp2, int yy, int xp,
                                            bool hasL, bool hasR, float2* r)
{
    if (yy < 0 || yy >= 128) {
        r[0] = make_float2(0.f, 0.f);
        r[1] = make_float2(0.f, 0.f);
        r[2] = make_float2(0.f, 0.f);
        return;
    }
    int ro = yy * 64;
    r[0] = hasL ? __half22float2(sp2[ro + xp - 1]) : make_float2(0.f, 0.f);
    r[1] = __half22float2(sp2[ro + xp]);
    r[2] = hasR ? __half22float2(sp2[ro + xp + 1]) : make_float2(0.f, 0.f);
}

__global__ __launch_bounds__(256)
void dwconv_plane(const __half* __restrict__ in,
                  const float* __restrict__ wdw,
                  __half* __restrict__ out,
                  float* __restrict__ sumsq)
{
    __shared__ __half sp[16384];
    __shared__ float wred[8];
    const int ch = blockIdx.x;
    const int b  = blockIdx.y;
    const int t  = threadIdx.x;
    const __half* ip = in + ((long)b * C3 + ch) * HW;

#pragma unroll
    for (int i = 0; i < 8; i++) {
        int off = (i * 256 + t) * 8;
        *(uint4*)&sp[off] = *(const uint4*)&ip[off];
    }
    float w[9];
#pragma unroll
    for (int i = 0; i < 9; i++) w[i] = __ldg(&wdw[ch * 9 + i]);
    __syncthreads();

    const __half2* sp2 = (const __half2*)sp;
    unsigned* op = (unsigned*)(out + ((long)b * C3 + ch) * HW);
    float ss = 0.f;

    const int xp = t & 63;          // half2 column 0..63
    const int y0 = (t >> 6) * 32;   // 32-row strip
    const bool hasL = (xp >= 1);
    const bool hasR = (xp <= 62);

#pragma unroll
    for (int par = 0; par < 2; par++) {
        const int ybase = y0 + par;
        float2 rows[3][3];
        dw_load_row(sp2, ybase - 2, xp, hasL, hasR, rows[0]);
        dw_load_row(sp2, ybase,     xp, hasL, hasR, rows[1]);
#pragma unroll
        for (int j = 0; j < 16; j++) {
            const int y = ybase + 2 * j;
            dw_load_row(sp2, y + 2, xp, hasL, hasR, rows[(j + 2) % 3]);
            const float2* top = rows[j % 3];
            const float2* mid = rows[(j + 1) % 3];
            const float2* bot = rows[(j + 2) % 3];
            float a0 = 0.f, a1 = 0.f;
            a0 += w[0] * top[0].x + w[1] * top[1].x + w[2] * top[2].x;
            a1 += w[0] * top[0].y + w[1] * top[1].y + w[2] * top[2].y;
            a0 += w[3] * mid[0].x + w[4] * mid[1].x + w[5] * mid[2].x;
            a1 += w[3] * mid[0].y + w[4] * mid[1].y + w[5] * mid[2].y;
            a0 += w[6] * bot[0].x + w[7] * bot[1].x + w[8] * bot[2].x;
            a1 += w[6] * bot[0].y + w[7] * bot[1].y + w[8] * bot[2].y;
            op[y * 64 + xp] = pkh(a0, a1);
            ss += a0 * a0 + a1 * a1;
        }
    }

    if (ch < 384) {
#pragma unroll
        for (int off = 16; off; off >>= 1)
            ss += __shfl_down_sync(0xffffffffu, ss, off);
        if ((t & 31) == 0) wred[t >> 5] = ss;
        __syncthreads();
        if (t == 0) {
            float s = 0.f;
#pragma unroll
            for (int i = 0; i < 8; i++) s += wred[i];
            sumsq[b * 384 + ch] = s;
        }
    }
}

// ---------------------------------------------------------------------------
// Tensor-core qk: S = q.k^T (24x24 per (b,h)), KSPL-way K split. (proven)
#define QAST 132
__global__ __launch_bounds__(256)
void qk_mma(const __half* __restrict__ qkv, float* __restrict__ Spart)
{
    __shared__ unsigned Aq[32 * QAST];   // q rows 0..23 + zero pad 24..31
    __shared__ unsigned Bk[24 * QAST];   // k rows
    __shared__ float Sred[8][576];

    const int split = blockIdx.x;        // 0..KSPL-1
    const int bh    = blockIdx.y;        // 0..63
    const int b = bh >> 3, h = bh & 7;
    const __half* qp = qkv + ((long)b * C3 + h * 24) * HW;
    const __half* kp = qkv + ((long)b * C3 + 192 + h * 24) * HW;
    const int t = threadIdx.x;
    const int wid = t >> 5, lane = t & 31;
    const int g = lane >> 2, tig = lane & 3;

    for (int i = t; i < 8 * QAST; i += 256) Aq[24 * QAST + i] = 0;

    float c[2][3][4];
#pragma unroll
    for (int i = 0; i < 2; i++)
#pragma unroll
        for (int j = 0; j < 3; j++)
#pragma unroll
            for (int q = 0; q < 4; q++) c[i][j][q] = 0.f;

    int n0 = split * (HW / KSPL);
    const int stages = (HW / KSPL) / 256;
    for (int st = 0; st < stages; st++, n0 += 256) {
        __syncthreads();
#pragma unroll
        for (int j = 0; j < 6; j++) {
            int gi = j * 256 + t;
            int isk = gi >= 768;
            int li = isk ? gi - 768 : gi;
            int r = li >> 5, c4 = li & 31;
            const __half* src = (isk ? kp : qp) + (long)r * HW + n0 + c4 * 8;
            uint4 v = *(const uint4*)src;
            unsigned* dst = (isk ? Bk : Aq) + r * QAST + c4 * 4;
            *(uint4*)dst = v;
        }
        __syncthreads();

#pragma unroll
        for (int s2 = 0; s2 < 2; s2++) {
            int kp0 = s2 * 64 + wid * 8;
            unsigned a[2][4];
#pragma unroll
            for (int m2 = 0; m2 < 2; m2++) {
                int rb = m2 * 16;
                a[m2][0] = Aq[(rb + g) * QAST + kp0 + tig];
                a[m2][1] = Aq[(rb + g + 8) * QAST + kp0 + tig];
                a[m2][2] = Aq[(rb + g) * QAST + kp0 + tig + 4];
                a[m2][3] = Aq[(rb + g + 8) * QAST + kp0 + tig + 4];
            }
#pragma unroll
            for (int nt = 0; nt < 3; nt++) {
                int gc = nt * 8 + g;
                unsigned b0 = Bk[gc * QAST + kp0 + tig];
                unsigned b1 = Bk[gc * QAST + kp0 + tig + 4];
#pragma unroll
                for (int m2 = 0; m2 < 2; m2++)
                    mma_f16(c[m2][nt], a[m2], b0, b1);
            }
        }
    }

#pragma unroll
    for (int m2 = 0; m2 < 2; m2++)
#pragma unroll
        for (int hf = 0; hf < 2; hf++) {
            int row = m2 * 16 + hf * 8 + g;
            if (row < 24) {
#pragma unroll
                for (int nt = 0; nt < 3; nt++) {
                    int col = nt * 8 + 2 * tig;
                    *(float2*)&Sred[wid][row * 24 + col] =
                        make_float2(c[m2][nt][hf * 2], c[m2][nt][hf * 2 + 1]);
                }
            }
        }
    __syncthreads();

    float* sp = Spart + ((long)bh * KSPL + split) * 576;
    for (int i = t; i < 576; i += 256) {
        float s01 = Sred[0][i] + Sred[1][i];
        float s23 = Sred[2][i] + Sred[3][i];
        float s45 = Sred[4][i] + Sred[5][i];
        float s67 = Sred[6][i] + Sred[7][i];
        sp[i] = (s01 + s23) + (s45 + s67);
    }
}

// ---------------------------------------------------------------------------
// Per (b,head): reduce split-K, normalize, softmax, fold w_proj -> fp16 W2.
__global__ void softmax_fold_kernel(const float* __restrict__ Spart,
                                    const float* __restrict__ sumsq,
                                    const float* __restrict__ temp,
                                    const float* __restrict__ wproj,
                                    unsigned* __restrict__ W2h)
{
    const int bh = blockIdx.x;          // 0..63
    const int b = bh >> 3, h = bh & 7;
    const int t = threadIdx.x;          // 256
    __shared__ float A[576];
    __shared__ float nq[24], nk[24];
    if (t < 24)
        nq[t] = sqrtf(sumsq[b * 384 + h * 24 + t]) + 1e-6f;
    else if (t < 48)
        nk[t - 24] = sqrtf(sumsq[b * 384 + 192 + h * 24 + (t - 24)]) + 1e-6f;
    __syncthreads();
    const float tmp = temp[h];
    for (int r = t; r < 576; r += 256) {
        int cidx = r / 24, d = r % 24;
        float s = 0.f;
#pragma unroll
        for (int ck = 0; ck < KSPL; ck++)
            s += Spart[((long)bh * KSPL + ck) * 576 + r];
        A[r] = s / (nq[cidx] * nk[d]) * tmp;
    }
    __syncthreads();
    if (t < 24) {
        float* row = &A[t * 24];
        float m = row[0];
        for (int d = 1; d < 24; d++) m = fmaxf(m, row[d]);
        float s = 0.f;
        for (int d = 0; d < 24; d++) { float e = expf(row[d] - m); row[d] = e; s += e; }
        float inv = 1.f / s;
        for (int d = 0; d < 24; d++) row[d] *= inv;
    }
    __syncthreads();
    for (int idx = t; idx < 192 * 12; idx += 256) {
        int o = idx / 12, jj = idx % 12;
        int d0 = 2 * jj;
        float s0 = 0.f, s1 = 0.f;
#pragma unroll
        for (int cidx = 0; cidx < 24; cidx++) {
            float wv = wproj[o * CC + h * 24 + cidx];
            s0 += wv * A[cidx * 24 + d0];
            s1 += wv * A[cidx * 24 + d0 + 1];
        }
        W2h[((long)b * CC + o) * 96 + h * 12 + jj] = pkh(s0, s1);
    }
}

// ---------------------------------------------------------------------------
extern "C" void kernel_launch(void* const* d_in, const int* in_sizes, int n_in,
                              void* d_out, int out_size)
{
    const float* x      = (const float*)d_in[0];
    const float* w_qkv  = (const float*)d_in[1];
    const float* w_dw   = (const float*)d_in[2];
    const float* w_proj = (const float*)d_in[3];
    const float* temp   = (const float*)d_in[4];
    float* out = (float*)d_out;

    __half *qkv_pre, *qkv_post;
    unsigned *wh, *W2h;
    float *sumsq, *Spart;
    cudaGetSymbolAddress((void**)&qkv_pre,  g_qkv_pre);
    cudaGetSymbolAddress((void**)&qkv_post, g_qkv_post);
    cudaGetSymbolAddress((void**)&wh,       g_wh);
    cudaGetSymbolAddress((void**)&W2h,      g_W2h);
    cudaGetSymbolAddress((void**)&sumsq,    g_sumsq);
    cudaGetSymbolAddress((void**)&Spart,    g_Spart);

    const int SMEM = (96 * BST + 2 * 64 * AST) * 4;  // 103424 B
    cudaFuncSetAttribute(gemm_nres,
                         cudaFuncAttributeMaxDynamicSharedMemorySize, SMEM);

    presplit_w<<<(576 * 96 + 255) / 256, 256>>>(w_qkv, wh);

    // K1: qkv = w_qkv @ x  -> fp16 (B resident, double-buffered A)
    gemm_nres<<<dim3(HW / 128, NB), 256, SMEM>>>(
        wh, 0L, x, (long)CC * HW, qkv_pre, (long)C3 * HW, C3, HW, 2, 1);

    // K2: depthwise conv (rolling-row register reuse) + block-reduced sumsq
    dwconv_plane<<<dim3(C3, NB), 256>>>(qkv_pre, w_dw, qkv_post, sumsq);

    // K3: tensor-core q.k^T (KSPL=8)
    qk_mma<<<dim3(KSPL, 64), 256>>>(qkv_post, Spart);

    // K4: per-(b,h) normalize + softmax + fold -> packed fp16 W2
    softmax_fold_kernel<<<64, 256>>>(Spart, sumsq, temp, w_proj, W2h);

    // K5: out = W2 @ v  (B = v resident fp16), fp32 out
    gemm_nres<<<dim3(HW / 128, NB), 256, SMEM>>>(
        W2h, (long)CC * 96, qkv_post + 384L * HW, (long)C3 * HW,
        out, (long)CC * HW, CC, HW, 1, 0);
}